// round 2
// baseline (speedup 1.0000x reference)
#include <cuda_runtime.h>

#define NROWS   341
#define CSTRIDE 16
#define TPB     256
#define NSAMP   262144

// Precomputed constrained coefficient rows, padded to 16 floats/row.
// Row layout: dim0 row at 0, dim1 rows [1,5), dim2 [5,21), dim3 [21,85), dim4 [85,341).
// Column 15 is 0 (so the padded float4 FMA leaves acc[15]==1 exact).
__device__ float gC[NROWS * CSTRIDE];

// ---------------------------------------------------------------------------
// Prep: constrained(A) = 2*(sigmoid(cumsum(softplus(A), axis=1)) - 0.5)
// ---------------------------------------------------------------------------
__global__ void bf_prep(const float* __restrict__ A0, const float* __restrict__ A1,
                        const float* __restrict__ A2, const float* __restrict__ A3,
                        const float* __restrict__ A4) {
    int r = threadIdx.x;
    if (r >= NROWS) return;
    const float* A; int lr;
    if (r == 0)      { A = A0; lr = 0;      }
    else if (r < 5)  { A = A1; lr = r - 1;  }
    else if (r < 21) { A = A2; lr = r - 5;  }
    else if (r < 85) { A = A3; lr = r - 21; }
    else             { A = A4; lr = r - 85; }
    float s = 0.f;
    for (int m = 0; m < 15; m++) {
        float a  = A[lr * 15 + m];
        float sp = (a > 20.f) ? a : log1pf(expf(a));   // softplus
        s += sp;                                        // cumsum
        float sig = 1.f / (1.f + expf(-s));
        gC[r * CSTRIDE + m] = 2.f * (sig - 0.5f);
    }
    gC[r * CSTRIDE + 15] = 0.f;
}

// ---------------------------------------------------------------------------
// Derivative eval: f = sum_m dcoef[m] * 16*C(15,m) * u^m v^(15-m)
// Horner-like: F_k = u*F_{k+1} + s_k * v^(15-k), running vp = v^(15-m).
// ---------------------------------------------------------------------------
__device__ __forceinline__ float deriv16(const float acc[16], float xi) {
    const float comb16[16] = {16.f, 240.f, 1680.f, 7280.f, 21840.f, 48048.f,
                              80080.f, 102960.f, 102960.f, 80080.f, 48048.f,
                              21840.f, 7280.f, 1680.f, 240.f, 16.f};
    float u = xi, v = 1.f - xi;
    float F  = (acc[15] - acc[14]) * comb16[15];
    float vp = 1.f;
#pragma unroll
    for (int m = 14; m >= 0; m--) {
        float prev = (m > 0) ? acc[m - 1] : 0.f;
        float sm   = (acc[m] - prev) * comb16[m];
        vp *= v;
        F = fmaf(u, F, sm * vp);
    }
    return F;
}

// One coefficient row: acc[0..14] += w * C[row][0..14]  (element 15 skipped; it's 0)
__device__ __forceinline__ void row_fma(const float* __restrict__ sC, int row,
                                        float w, float acc[16]) {
    const float4* p = reinterpret_cast<const float4*>(sC + row * CSTRIDE);
#pragma unroll
    for (int q = 0; q < 3; q++) {
        float4 c = p[q];
        acc[4*q + 0] = fmaf(w, c.x, acc[4*q + 0]);
        acc[4*q + 1] = fmaf(w, c.y, acc[4*q + 1]);
        acc[4*q + 2] = fmaf(w, c.z, acc[4*q + 2]);
        acc[4*q + 3] = fmaf(w, c.w, acc[4*q + 3]);
    }
    float4 c3 = p[3];
    acc[12] = fmaf(w, c3.x, acc[12]);
    acc[13] = fmaf(w, c3.y, acc[13]);
    acc[14] = fmaf(w, c3.z, acc[14]);
    // acc[15] untouched: stays exactly 1
}

// ---------------------------------------------------------------------------
// Main kernel: one thread per sample
// ---------------------------------------------------------------------------
__global__ void __launch_bounds__(TPB)
bf_main(const float* __restrict__ x, float* __restrict__ out) {
    __shared__ __align__(16) float sC[NROWS * CSTRIDE];
    __shared__ float sX[TPB * 5];

    const int tid  = threadIdx.x;
    const int base = blockIdx.x * TPB;

    for (int i = tid; i < NROWS * CSTRIDE; i += TPB) sC[i] = gC[i];
#pragma unroll
    for (int i = 0; i < 5; i++) sX[tid + i * TPB] = x[base * 5 + tid + i * TPB];
    __syncthreads();

    float xv[5];
#pragma unroll
    for (int j = 0; j < 5; j++) xv[j] = sX[tid * 5 + j];

    // degree-3 Bernstein bases for conditioner coords 0..3
    float b[4][4];
#pragma unroll
    for (int j = 0; j < 4; j++) {
        float u = xv[j], v = 1.f - u;
        b[j][0] = v * v * v;
        b[j][1] = 3.f * u * v * v;
        b[j][2] = 3.f * u * u * v;
        b[j][3] = u * u * u;
    }

    float density;

    // ---- dim 0 (rowbase 0, single row, weight 1)
    {
        float acc[16];
#pragma unroll
        for (int m = 0; m < 15; m++) acc[m] = sC[m];
        acc[15] = 1.f;
        density = deriv16(acc, xv[0]);
    }

    // ---- dim 1 (rowbase 1)
    {
        float acc[16];
#pragma unroll
        for (int m = 0; m < 15; m++) acc[m] = 0.f;
        acc[15] = 1.f;
#pragma unroll
        for (int k0 = 0; k0 < 4; k0++)
            row_fma(sC, 1 + k0, b[0][k0], acc);
        density *= deriv16(acc, xv[1]);
    }

    // ---- dim 2 (rowbase 5)
    {
        float acc[16];
#pragma unroll
        for (int m = 0; m < 15; m++) acc[m] = 0.f;
        acc[15] = 1.f;
#pragma unroll
        for (int k0 = 0; k0 < 4; k0++) {
            float w0 = b[0][k0];
#pragma unroll
            for (int k1 = 0; k1 < 4; k1++) {
                float w = w0 * b[1][k1];
                row_fma(sC, 5 + k0 * 4 + k1, w, acc);
            }
        }
        density *= deriv16(acc, xv[2]);
    }

    // ---- dim 3 (rowbase 21)
    {
        float acc[16];
#pragma unroll
        for (int m = 0; m < 15; m++) acc[m] = 0.f;
        acc[15] = 1.f;
#pragma unroll
        for (int k0 = 0; k0 < 4; k0++) {
            float w0 = b[0][k0];
#pragma unroll
            for (int k1 = 0; k1 < 4; k1++) {
                float w1 = w0 * b[1][k1];
#pragma unroll
                for (int k2 = 0; k2 < 4; k2++) {
                    float w = w1 * b[2][k2];
                    row_fma(sC, 21 + (k0 * 4 + k1) * 4 + k2, w, acc);
                }
            }
        }
        density *= deriv16(acc, xv[3]);
    }

    // ---- dim 4 (rowbase 85)
    {
        float acc[16];
#pragma unroll
        for (int m = 0; m < 15; m++) acc[m] = 0.f;
        acc[15] = 1.f;
#pragma unroll
        for (int k0 = 0; k0 < 4; k0++) {
            float w0 = b[0][k0];
#pragma unroll
            for (int k1 = 0; k1 < 4; k1++) {
                float w1 = w0 * b[1][k1];
#pragma unroll
                for (int k2 = 0; k2 < 4; k2++) {
                    float w2 = w1 * b[2][k2];
#pragma unroll
                    for (int k3 = 0; k3 < 4; k3++) {
                        float w = w2 * b[3][k3];
                        row_fma(sC, 85 + ((k0 * 4 + k1) * 4 + k2) * 4 + k3, w, acc);
                    }
                }
            }
        }
        density *= deriv16(acc, xv[4]);
    }

    out[base + tid] = density;
}

// ---------------------------------------------------------------------------
extern "C" void kernel_launch(void* const* d_in, const int* in_sizes, int n_in,
                              void* d_out, int out_size) {
    const float* x  = (const float*)d_in[0];
    const float* A0 = (const float*)d_in[1];
    const float* A1 = (const float*)d_in[2];
    const float* A2 = (const float*)d_in[3];
    const float* A3 = (const float*)d_in[4];
    const float* A4 = (const float*)d_in[5];
    float* out = (float*)d_out;

    bf_prep<<<1, 352>>>(A0, A1, A2, A3, A4);
    bf_main<<<NSAMP / TPB, TPB>>>(x, out);
}